// round 6
// baseline (speedup 1.0000x reference)
#include <cuda_runtime.h>

// Problem geometry (fixed by the reference)
#define WIDTH   1000
#define HEIGHT  1000
#define PS      5
#define NT      10
#define PPR     (WIDTH / PS)          // 200 patches per patch-row
#define NPIX    (WIDTH * HEIGHT)      // 1,000,000

constexpr int THREADS    = 128;
constexpr int NCOLTHREADS = PPR * WIDTH;   // 200 patch-rows x 1000 cols = 200,000 threads

using ull = unsigned long long;

// Packed dual-FMA on the f32x2 pipe (ptxas never auto-fuses this).
__device__ __forceinline__ ull fma2(ull a, ull b, ull c) {
    ull d;
    asm("fma.rn.f32x2 %0, %1, %2, %3;" : "=l"(d) : "l"(a), "l"(b), "l"(c));
    return d;
}
__device__ __forceinline__ void unpack2(ull h, float& lo, float& hi) {
    asm("mov.b64 {%0, %1}, %2;" : "=f"(lo), "=f"(hi) : "l"(h));
}

__global__ __launch_bounds__(THREADS)
void ts_approx_kernel(const float* __restrict__ pix,     // [NPIX, 2]
                      const float* __restrict__ coef,    // [NPATCH, 3, NT, 2]
                      const float* __restrict__ bias,    // [NPATCH, 3]
                      float* __restrict__ out)           // [3, NPIX]
{
    const int g = blockIdx.x * THREADS + threadIdx.x;
    if (g >= NCOLTHREADS) return;

    // Thread -> (patch-row, column). One thread = 5 vertical pixels = ONE patch.
    const int pr  = g / WIDTH;            // 0..199
    const int c   = g - pr * WIDTH;       // 0..999
    const int pat = pr * PPR + c / PS;    // global patch index
    const int n0  = (pr * PS) * WIDTH + c;

    // ── Issue ALL loads up front: 5 pixel pairs + 15 coeff float4 + bias.
    //    MLP ~ 20 per thread; one DRAM round-trip covers everything.
    const ull* __restrict__ pixq = reinterpret_cast<const ull*>(pix);
    ull xy[PS];
    #pragma unroll
    for (int r = 0; r < PS; r++)
        xy[r] = __ldcs(&pixq[n0 + r * WIDTH]);   // streaming: read-once

    // Coefficients: 240B per patch; 5 lanes share a patch -> L1 broadcast,
    // 25 threads per patch dedup in L1/L2 -> DRAM traffic unchanged.
    const ulonglong2* __restrict__ cfc =
        reinterpret_cast<const ulonglong2*>(coef) + (size_t)pat * 15;
    ulonglong2 u[15];
    #pragma unroll
    for (int i = 0; i < 15; i++)
        u[i] = cfc[i];

    float bg[3];
    #pragma unroll
    for (int ch = 0; ch < 3; ch++)
        bg[ch] = bias[pat * 3 + ch];

    // ── Straight-line compute: 3 channels x 5 rows of packed Horner (ILP 5).
    #pragma unroll
    for (int ch = 0; ch < 3; ch++) {
        const ulonglong2 u0 = u[ch * 5 + 0];   // (c0, c1) pairs (a_t, b_t)
        const ulonglong2 u1 = u[ch * 5 + 1];
        const ulonglong2 u2 = u[ch * 5 + 2];
        const ulonglong2 u3 = u[ch * 5 + 3];
        const ulonglong2 u4 = u[ch * 5 + 4];
        const float bch = bg[ch];

        #pragma unroll
        for (int r = 0; r < PS; r++) {
            ull h = u4.y;                  // (a9, b9)
            h = fma2(h, xy[r], u4.x);
            h = fma2(h, xy[r], u3.y);
            h = fma2(h, xy[r], u3.x);
            h = fma2(h, xy[r], u2.y);
            h = fma2(h, xy[r], u2.x);
            h = fma2(h, xy[r], u1.y);
            h = fma2(h, xy[r], u1.x);
            h = fma2(h, xy[r], u0.y);
            h = fma2(h, xy[r], u0.x);      // + (a0, b0)
            float hx, hy;
            unpack2(h, hx, hy);
            __stcs(&out[(size_t)ch * NPIX + n0 + r * WIDTH], hx + (hy + bch));
        }
    }
}

extern "C" void kernel_launch(void* const* d_in, const int* in_sizes, int n_in,
                              void* d_out, int out_size)
{
    const float* pix  = (const float*)d_in[0];   // [1e6, 2]
    const float* coef = (const float*)d_in[1];   // [40000, 3, 10, 2]
    const float* bias = (const float*)d_in[2];   // [40000, 3]
    float* out        = (float*)d_out;           // [3, 1e6]

    const int nblocks = (NCOLTHREADS + THREADS - 1) / THREADS;   // 1563
    ts_approx_kernel<<<nblocks, THREADS>>>(pix, coef, bias, out);
}

// round 7
// speedup vs baseline: 1.0281x; 1.0281x over previous
#include <cuda_runtime.h>

// Problem geometry (fixed by the reference)
#define WIDTH   1000
#define HEIGHT  1000
#define PS      5
#define NT      10
#define PPR     (WIDTH / PS)          // 200 patches per patch-row
#define NPIX    (WIDTH * HEIGHT)      // 1,000,000

constexpr int PATCHES_PER_STRIP = 25;
constexpr int COLS_PER_STRIP    = PATCHES_PER_STRIP * PS;   // 125
constexpr int SEGS              = WIDTH / COLS_PER_STRIP;   // 8
constexpr int STRIPS_PER_BLOCK  = 2;
constexpr int THREADS           = 128;
constexpr int COEF_PER_PATCH    = 3 * NT * 2;               // 60 floats = 240 B
constexpr int COEF_VEC16        = PATCHES_PER_STRIP * COEF_PER_PATCH / 4; // 375

using ull = unsigned long long;

// Packed dual-FMA on the f32x2 pipe (ptxas never auto-fuses this).
__device__ __forceinline__ ull fma2(ull a, ull b, ull c) {
    ull d;
    asm("fma.rn.f32x2 %0, %1, %2, %3;" : "=l"(d) : "l"(a), "l"(b), "l"(c));
    return d;
}
__device__ __forceinline__ void unpack2(ull h, float& lo, float& hi) {
    asm("mov.b64 {%0, %1}, %2;" : "=f"(lo), "=f"(hi) : "l"(h));
}
__device__ __forceinline__ void cp_async16(void* smem_dst, const void* gmem_src) {
    unsigned saddr = (unsigned)__cvta_generic_to_shared(smem_dst);
    asm volatile("cp.async.cg.shared.global [%0], [%1], 16;" :: "r"(saddr), "l"(gmem_src));
}

__global__ __launch_bounds__(THREADS, 8)
void ts_approx_kernel(const float* __restrict__ pix,     // [NPIX, 2]
                      const float* __restrict__ coef,    // [NPATCH, 3, NT, 2]
                      const float* __restrict__ bias,    // [NPATCH, 3]
                      float* __restrict__ out)           // [3, NPIX]
{
    __shared__ float s_coef[2][PATCHES_PER_STRIP * COEF_PER_PATCH]; // 2 x 6000 B

    const int b    = blockIdx.x;
    const int pr   = b / (SEGS / STRIPS_PER_BLOCK);   // patch-row 0..199
    const int pp   = b % (SEGS / STRIPS_PER_BLOCK);   // strip-pair 0..3
    const int seg0 = pp * STRIPS_PER_BLOCK;           // first of 2 adjacent strips
    const int row0 = pr * PS;
    const int c    = threadIdx.x;                     // 0..124 active

    const ull* __restrict__ pixq = reinterpret_cast<const ull*>(pix);

    auto stage = [&](int s) {   // cp.async one strip's coefficients into buf s
        const int patch0 = pr * PPR + (seg0 + s) * PATCHES_PER_STRIP;
        const float4* gc = reinterpret_cast<const float4*>(coef + (size_t)patch0 * COEF_PER_PATCH);
        float4* sc = reinterpret_cast<float4*>(s_coef[s]);
        #pragma unroll
        for (int i = threadIdx.x; i < COEF_VEC16; i += THREADS)
            cp_async16(sc + i, gc + i);
        asm volatile("cp.async.commit_group;" ::: "memory");
    };

    auto load_pix = [&](int s, ull (&xy)[PS]) {
        const int n0 = row0 * WIDTH + (seg0 + s) * COLS_PER_STRIP + c;
        #pragma unroll
        for (int r = 0; r < PS; r++)
            xy[r] = __ldcs(&pixq[n0 + r * WIDTH]);
    };

    // ── Prologue: stage strip0 coeffs + strip0 pixels, then immediately stage strip1.
    stage(0);
    ull xy_cur[PS];
    if (c < COLS_PER_STRIP) load_pix(0, xy_cur);
    stage(1);

    #pragma unroll
    for (int s = 0; s < STRIPS_PER_BLOCK; s++) {
        if (s == 0)
            asm volatile("cp.async.wait_group 1;" ::: "memory"); // buf0 ready, buf1 in flight
        else
            asm volatile("cp.async.wait_group 0;" ::: "memory"); // buf1 ready
        __syncthreads();

        // Prefetch next strip's pixels; LDGs fly during this strip's compute.
        ull xy_next[PS];
        if (s + 1 < STRIPS_PER_BLOCK && c < COLS_PER_STRIP)
            load_pix(s + 1, xy_next);

        if (c < COLS_PER_STRIP) {
            const int pl  = c / PS;                          // local patch 0..24
            const int pat = pr * PPR + (seg0 + s) * PATCHES_PER_STRIP + pl;
            const int n0  = row0 * WIDTH + (seg0 + s) * COLS_PER_STRIP + c;

            #pragma unroll
            for (int ch = 0; ch < 3; ch++) {
                // 5 x 16B smem loads; lane stride 240B -> conflict-free.
                const ulonglong2* cfc =
                    reinterpret_cast<const ulonglong2*>(s_coef[s]) + pl * 15 + ch * 5;
                const ulonglong2 u0 = cfc[0];
                const ulonglong2 u1 = cfc[1];
                const ulonglong2 u2 = cfc[2];
                const ulonglong2 u3 = cfc[3];
                const ulonglong2 u4 = cfc[4];
                const float bch = __ldg(&bias[pat * 3 + ch]);  // L1-broadcast, 5 lanes share

                #pragma unroll
                for (int r = 0; r < PS; r++) {
                    ull h = u4.y;                  // (a9, b9)
                    h = fma2(h, xy_cur[r], u4.x);
                    h = fma2(h, xy_cur[r], u3.y);
                    h = fma2(h, xy_cur[r], u3.x);
                    h = fma2(h, xy_cur[r], u2.y);
                    h = fma2(h, xy_cur[r], u2.x);
                    h = fma2(h, xy_cur[r], u1.y);
                    h = fma2(h, xy_cur[r], u1.x);
                    h = fma2(h, xy_cur[r], u0.y);
                    h = fma2(h, xy_cur[r], u0.x);  // + (a0, b0)
                    float hx, hy;
                    unpack2(h, hx, hy);
                    __stcs(&out[(size_t)ch * NPIX + n0 + r * WIDTH], hx + (hy + bch));
                }
            }
        }

        if (s + 1 < STRIPS_PER_BLOCK) {
            #pragma unroll
            for (int r = 0; r < PS; r++) xy_cur[r] = xy_next[r];
        }
        // Distinct buffers per strip: no trailing barrier needed.
    }
}

extern "C" void kernel_launch(void* const* d_in, const int* in_sizes, int n_in,
                              void* d_out, int out_size)
{
    const float* pix  = (const float*)d_in[0];   // [1e6, 2]
    const float* coef = (const float*)d_in[1];   // [40000, 3, 10, 2]
    const float* bias = (const float*)d_in[2];   // [40000, 3]
    float* out        = (float*)d_out;           // [3, 1e6]

    const int nblocks = (HEIGHT / PS) * (SEGS / STRIPS_PER_BLOCK);  // 200 * 4 = 800
    ts_approx_kernel<<<nblocks, THREADS>>>(pix, coef, bias, out);
}